// round 12
// baseline (speedup 1.0000x reference)
#include <cuda_runtime.h>
#include <cuda.h>
#include <cuda_fp16.h>
#include <math.h>

// ---------------------------------------------------------------------------
// HashGridT: Instant-NGP 2D multires hash encoding + temporal interpolation
//
//   K1: blend the two time slices into one device-global fp16 table (512 KB).
//   K2 (R12 restructure): WARP-AUTONOMOUS pipeline. R5/R10/R11 each bought
//       only ~5% from latency fixes while no pipe exceeded 52% -> the binder
//       was the per-tile CTA-wide coupling (2 x __syncthreads + straggler
//       max-over-warps + thread-0 serially issuing all TMA boxes, ~35x).
//       Now each warp owns: a 64-point group (2 pts/lane), a private
//       double-buffered 2x1KB smem slice, and its own TMA bulk-group
//       counter (lane 0). Zero CTA-wide barriers after init; only
//       __syncwarp. 512 thr x 2 CTAs/SM (96 KB smem), grid (37,8)=296.
// ---------------------------------------------------------------------------

#define N_LEVELS     8
#define HASHMAP_SIZE 8192
#define HASH_MASK    8191u
#define PRIME_Y      2654435761u
#define TIME_RES     25
#define THREADS      512
#define WARPS        (THREADS / 32)
#define GROUP        64              // points per warp-group (2 per lane)

struct __align__(8) H4 { __half2 lo, hi; };

// Blended fp16 table: [level][hash] 4 feats. 512 KB static device global.
__device__ H4 g_btable_h[N_LEVELS * HASHMAP_SIZE];

// ---------------------------------------------------------------------------
// Kernel 1: temporal blend of the hash table (fp32 math, one fp16 round).
// ---------------------------------------------------------------------------
__global__ void blend_table_kernel(const float* __restrict__ table,
                                   const float* __restrict__ t_ptr) {
    int i = blockIdx.x * blockDim.x + threadIdx.x;  // 0 .. 65535

    float t   = *t_ptr;
    float idx = t * (float)(TIME_RES - 1);
    float fi1 = floorf(idx);
    float fi2 = ceilf(idx);
    int i1 = min(max((int)fi1, 0), TIME_RES - 1);
    int i2 = min(max((int)fi2, 0), TIME_RES - 1);
    float w2 = idx - fi1;
    float w1 = 1.0f - w2;

    const float4* tab = (const float4*)table;
    float4 a = tab[(size_t)i1 * (N_LEVELS * HASHMAP_SIZE) + i];
    float4 b = tab[(size_t)i2 * (N_LEVELS * HASHMAP_SIZE) + i];

    H4 h;
    h.lo = __floats2half2_rn(w1 * a.x + w2 * b.x, w1 * a.y + w2 * b.y);
    h.hi = __floats2half2_rn(w1 * a.z + w2 * b.z, w1 * a.w + w2 * b.w);
    g_btable_h[i] = h;
}

// ---------------------------------------------------------------------------
// Bilinear gather + blend for one point at one level (fp16 SMEM table,
// fp32 arithmetic).
// ---------------------------------------------------------------------------
__device__ __forceinline__ float4 encode_one(const H4* __restrict__ s_tab,
                                             float xc, float yc, float scale) {
    // Match numpy's mul-then-add rounding (no FMA contraction).
    float px = __fadd_rn(__fmul_rn(xc, scale), 0.5f);
    float py = __fadd_rn(__fmul_rn(yc, scale), 0.5f);
    float fx = floorf(px);
    float fy = floorf(py);
    float wx = px - fx;
    float wy = py - fy;

    unsigned ix = (unsigned)(int)fx;
    unsigned iy = (unsigned)(int)fy;

    unsigned hy0 = iy * PRIME_Y;
    unsigned hy1 = hy0 + PRIME_Y;     // (iy+1)*PRIME_Y mod 2^32

    unsigned h00 = (ix        ^ hy0) & HASH_MASK;
    unsigned h10 = ((ix + 1u) ^ hy0) & HASH_MASK;
    unsigned h01 = (ix        ^ hy1) & HASH_MASK;
    unsigned h11 = ((ix + 1u) ^ hy1) & HASH_MASK;

    H4 q00 = s_tab[h00];
    H4 q10 = s_tab[h10];
    H4 q01 = s_tab[h01];
    H4 q11 = s_tab[h11];

    float2 f00l = __half22float2(q00.lo), f00h = __half22float2(q00.hi);
    float2 f10l = __half22float2(q10.lo), f10h = __half22float2(q10.hi);
    float2 f01l = __half22float2(q01.lo), f01h = __half22float2(q01.hi);
    float2 f11l = __half22float2(q11.lo), f11h = __half22float2(q11.hi);

    float ax = fmaf(wx, f10l.x - f00l.x, f00l.x);
    float ay = fmaf(wx, f10l.y - f00l.y, f00l.y);
    float az = fmaf(wx, f10h.x - f00h.x, f00h.x);
    float aw = fmaf(wx, f10h.y - f00h.y, f00h.y);
    float bx = fmaf(wx, f11l.x - f01l.x, f01l.x);
    float by = fmaf(wx, f11l.y - f01l.y, f01l.y);
    float bz = fmaf(wx, f11h.x - f01h.x, f01h.x);
    float bw = fmaf(wx, f11h.y - f01h.y, f01h.y);

    float4 r;
    r.x = fmaf(wy, bx - ax, ax);
    r.y = fmaf(wy, by - ay, ay);
    r.z = fmaf(wy, bz - az, az);
    r.w = fmaf(wy, bw - aw, aw);
    return r;
}

__device__ __forceinline__ uint32_t smem_u32(const void* p) {
    return (uint32_t)__cvta_generic_to_shared(p);
}

// ---------------------------------------------------------------------------
// Kernel 2 (warp-autonomous TMA store path).
// smem: [0,64KB) fp16 table, then WARPS x 2 x 64 float4 slices (32 KB).
// ---------------------------------------------------------------------------
__global__ void __launch_bounds__(THREADS, 2)
hash_encode_tma_kernel(const float2* __restrict__ x,
                       float4* __restrict__ out,      // tail fallback only
                       int N,
                       const __grid_constant__ CUtensorMap tmap)
{
    extern __shared__ char smem_raw[];
    H4*     s_tab   = (H4*)smem_raw;                           // 8192 entries
    float4* s_slice = (float4*)(smem_raw + HASHMAP_SIZE * 8);  // WARPS*2*GROUP

    const int level = blockIdx.y;
    const int tid   = threadIdx.x;
    const int wid   = tid >> 5;
    const int lid   = tid & 31;

    // Stage this level's blended fp16 table into SMEM (coalesced 8B).
    const H4* lt = g_btable_h + level * HASHMAP_SIZE;
    #pragma unroll
    for (int i = tid; i < HASHMAP_SIZE; i += THREADS)
        s_tab[i] = lt[i];
    __syncthreads();   // the ONLY CTA-wide barrier

    // Per-level scale, matching numpy float64 exp2 path then fp32 cast.
    const float scale = (float)(exp2((double)level * (6.0 / 7.0)) * 512.0 - 1.0);

    const int n_groups = (N + GROUP - 1) / GROUP;   // 31250 for N=2M (exact)
    const int gstride  = gridDim.x * WARPS;

    float4* slice0 = s_slice + (wid * 2) * GROUP;   // this warp's two buffers
    float4* slice1 = slice0 + GROUP;

    int g = blockIdx.x * WARPS + wid;

    // Preload group g's coordinates (2 points per lane, stride-32 coalesced).
    float2 c0, c1;
    if (g < n_groups) {
        const int base = g * GROUP;
        if (base + lid      < N) c0 = __ldg(&x[base + lid]);
        if (base + lid + 32 < N) c1 = __ldg(&x[base + lid + 32]);
    }

    int it = 0;
    for (; g < n_groups; g += gstride, ++it) {
        const int base = g * GROUP;
        const bool full = (base + GROUP <= N);

        // Prefetch next group's x first -- LDG latency hides under this
        // group's compute.
        const int gn = g + gstride;
        float2 n0, n1;
        if (gn < n_groups) {
            const int nb = gn * GROUP;
            if (nb + lid      < N) n0 = __ldg(&x[nb + lid]);
            if (nb + lid + 32 < N) n1 = __ldg(&x[nb + lid + 32]);
        }

        // Reuse guard: the buffer we are about to fill was handed to TMA
        // two iterations ago. Only lane 0 carries bulk-group state.
        if (lid == 0)
            asm volatile("cp.async.bulk.wait_group 1;" ::: "memory");
        __syncwarp();

        float4* buf = (it & 1) ? slice1 : slice0;

        if (full) {
            buf[lid]      = encode_one(s_tab, c0.x, c0.y, scale);
            buf[lid + 32] = encode_one(s_tab, c1.x, c1.y, scale);

            // Order this lane's STS (generic proxy) before TMA (async proxy).
            asm volatile("fence.proxy.async;" ::: "memory");
            __syncwarp();

            if (lid == 0) {
                asm volatile(
                    "cp.async.bulk.tensor.3d.global.shared::cta.tile.bulk_group"
                    " [%0, {%1, %2, %3}], [%4];"
                    :: "l"(&tmap), "r"(0), "r"(level), "r"(base),
                       "r"(smem_u32(buf))
                    : "memory");
                asm volatile("cp.async.bulk.commit_group;" ::: "memory");
            }
        } else {
            // Partial tail group (unused for N=2M): direct scattered stores.
            if (base + lid < N)
                out[(size_t)(base + lid) * N_LEVELS + level] =
                    encode_one(s_tab, c0.x, c0.y, scale);
            if (base + lid + 32 < N)
                out[(size_t)(base + lid + 32) * N_LEVELS + level] =
                    encode_one(s_tab, c1.x, c1.y, scale);
        }

        c0 = n0;
        c1 = n1;
    }

    // Drain this warp's pending TMA stores before exit.
    if (lid == 0)
        asm volatile("cp.async.bulk.wait_group 0;" ::: "memory");
    __syncwarp();
}

// ---------------------------------------------------------------------------
// Kernel 2 (legacy STG fallback) -- used only if tensormap creation fails.
// ---------------------------------------------------------------------------
__global__ void __launch_bounds__(1024, 1)
hash_encode_kernel(const float4* __restrict__ x2, float4* __restrict__ out, int P)
{
    extern __shared__ char smem_raw[];
    H4* s_tab = (H4*)smem_raw;
    const int level = blockIdx.y;
    const H4* lt = g_btable_h + level * HASHMAP_SIZE;
    #pragma unroll
    for (int i = threadIdx.x; i < HASHMAP_SIZE; i += 1024)
        s_tab[i] = lt[i];
    __syncthreads();

    const float scale = (float)(exp2((double)level * (6.0 / 7.0)) * 512.0 - 1.0);
    const int chunk = (P + gridDim.x - 1) / gridDim.x;
    const int m0 = blockIdx.x * chunk;
    const int m1 = min(m0 + chunk, P);

    for (int m = m0 + threadIdx.x; m < m1; m += 1024) {
        float4 p = __ldg(&x2[m]);
        float4 r0 = encode_one(s_tab, p.x, p.y, scale);
        float4 r1 = encode_one(s_tab, p.z, p.w, scale);
        size_t n = (size_t)m * 2;
        out[n * N_LEVELS + level]       = r0;
        out[(n + 1) * N_LEVELS + level] = r1;
    }
}

// ---------------------------------------------------------------------------
// Host: tensormap encode via driver entry point (cudart-only lookup).
// ---------------------------------------------------------------------------
typedef CUresult (*EncodeTiledFn)(
    CUtensorMap*, CUtensorMapDataType, cuuint32_t, void*,
    const cuuint64_t*, const cuuint64_t*, const cuuint32_t*, const cuuint32_t*,
    CUtensorMapInterleave, CUtensorMapSwizzle, CUtensorMapL2promotion,
    CUtensorMapFloatOOBfill);

static EncodeTiledFn get_encode_fn() {
    void* p = nullptr;
#if CUDART_VERSION >= 12000
    cudaDriverEntryPointQueryResult qr;
    if (cudaGetDriverEntryPoint("cuTensorMapEncodeTiled", &p,
                                cudaEnableDefault, &qr) != cudaSuccess)
        return nullptr;
#else
    if (cudaGetDriverEntryPoint("cuTensorMapEncodeTiled", &p,
                                cudaEnableDefault) != cudaSuccess)
        return nullptr;
#endif
    return (EncodeTiledFn)p;
}

extern "C" void kernel_launch(void* const* d_in, const int* in_sizes, int n_in,
                              void* d_out, int out_size) {
    const float* x_ptr = nullptr;
    const float* t_ptr = nullptr;
    const float* table_ptr = nullptr;
    int N = 0;

    const int TABLE_ELEMS = TIME_RES * N_LEVELS * HASHMAP_SIZE * 4;  // 6,553,600

    for (int i = 0; i < n_in; i++) {
        int s = in_sizes[i];
        if (s == 1)                    t_ptr = (const float*)d_in[i];
        else if (s == TABLE_ELEMS)     table_ptr = (const float*)d_in[i];
        else { x_ptr = (const float*)d_in[i]; N = s / 2; }
    }

    // K1: temporal blend -> g_btable_h (fp16).
    blend_table_kernel<<<(N_LEVELS * HASHMAP_SIZE) / 256, 256>>>(table_ptr, t_ptr);

    // TMA path: out viewed as (4 feats, 8 levels, N points); box (4,1,64).
    bool tma_ok = false;
    CUtensorMap tmap;
    EncodeTiledFn enc = get_encode_fn();
    if (enc) {
        cuuint64_t dims[3]    = {4, N_LEVELS, (cuuint64_t)N};
        cuuint64_t strides[2] = {16, 128};               // bytes, dims 1..2
        cuuint32_t box[3]     = {4, 1, GROUP};
        cuuint32_t estr[3]    = {1, 1, 1};
        CUresult r = enc(&tmap, CU_TENSOR_MAP_DATA_TYPE_FLOAT32, 3, d_out,
                         dims, strides, box, estr,
                         CU_TENSOR_MAP_INTERLEAVE_NONE,
                         CU_TENSOR_MAP_SWIZZLE_NONE,
                         CU_TENSOR_MAP_L2_PROMOTION_L2_128B,
                         CU_TENSOR_MAP_FLOAT_OOB_FILL_NONE);
        tma_ok = (r == CUDA_SUCCESS);
    }

    if (tma_ok) {
        // 64 KB table + 16 warps x 2 x 1 KB slices = 96 KB -> 2 CTAs/SM.
        const int SMEM = HASHMAP_SIZE * 8 + WARPS * 2 * GROUP * (int)sizeof(float4);
        cudaFuncSetAttribute(hash_encode_tma_kernel,
                             cudaFuncAttributeMaxDynamicSharedMemorySize, SMEM);
        dim3 grid(37, N_LEVELS);   // 296 CTAs = 2 per SM
        hash_encode_tma_kernel<<<grid, THREADS, SMEM>>>(
            (const float2*)x_ptr, (float4*)d_out, N, tmap);
    } else {
        const int SMEM = HASHMAP_SIZE * 8;               // 64 KB
        cudaFuncSetAttribute(hash_encode_kernel,
                             cudaFuncAttributeMaxDynamicSharedMemorySize, SMEM);
        int P = N / 2;
        dim3 grid(18, N_LEVELS);
        hash_encode_kernel<<<grid, 1024, SMEM>>>(
            (const float4*)x_ptr, (float4*)d_out, P);
    }
}

// round 13
// speedup vs baseline: 1.6621x; 1.6621x over previous
#include <cuda_runtime.h>
#include <cuda.h>
#include <cuda_fp16.h>
#include <math.h>

// ---------------------------------------------------------------------------
// HashGridT: Instant-NGP 2D multires hash encoding + temporal interpolation
//
//   K1: blend the two time slices into one device-global fp16 table (512 KB).
//   K2 (R13): TWO LEVELS PER CTA. R7-R11 plateaued ~150us across huge
//       compute-side changes -> invariant wall = TMA row processing of 16M
//       16B output rows (~2.4cyc/row/SM). Pairing adjacent levels in one CTA
//       makes each staged row 32B ([lo float4, hi float4] per point),
//       halving row count to 8M. Table = 2x64KB fp16 in SMEM; triple-
//       buffered 32KB staging; grid (37 chunks x 4 pairs) = 148 CTAs =
//       one wave at 1 CTA/SM; 1024 threads, 1 point/thread/tile.
//       CTA-wide tile structure kept from R11 (preserves L2 write-merging;
//       R12's warp-autonomy lost it and regressed).
// ---------------------------------------------------------------------------

#define N_LEVELS     8
#define HASHMAP_SIZE 8192
#define HASH_MASK    8191u
#define PRIME_Y      2654435761u
#define TIME_RES     25
#define THREADS      1024
#define TILE         1024            // points per CTA tile (1 per thread)
#define NBUF         3               // staging buffers (wait_group 2)
#define BOX_ROWS     128             // TMA box: (8 floats, 1 pair, 128 points)

struct __align__(8) H4 { __half2 lo, hi; };

// Blended fp16 table: [level][hash] 4 feats. 512 KB static device global.
__device__ H4 g_btable_h[N_LEVELS * HASHMAP_SIZE];

// ---------------------------------------------------------------------------
// Kernel 1: temporal blend of the hash table (fp32 math, one fp16 round).
// ---------------------------------------------------------------------------
__global__ void blend_table_kernel(const float* __restrict__ table,
                                   const float* __restrict__ t_ptr) {
    int i = blockIdx.x * blockDim.x + threadIdx.x;  // 0 .. 65535

    float t   = *t_ptr;
    float idx = t * (float)(TIME_RES - 1);
    float fi1 = floorf(idx);
    float fi2 = ceilf(idx);
    int i1 = min(max((int)fi1, 0), TIME_RES - 1);
    int i2 = min(max((int)fi2, 0), TIME_RES - 1);
    float w2 = idx - fi1;
    float w1 = 1.0f - w2;

    const float4* tab = (const float4*)table;
    float4 a = tab[(size_t)i1 * (N_LEVELS * HASHMAP_SIZE) + i];
    float4 b = tab[(size_t)i2 * (N_LEVELS * HASHMAP_SIZE) + i];

    H4 h;
    h.lo = __floats2half2_rn(w1 * a.x + w2 * b.x, w1 * a.y + w2 * b.y);
    h.hi = __floats2half2_rn(w1 * a.z + w2 * b.z, w1 * a.w + w2 * b.w);
    g_btable_h[i] = h;
}

// ---------------------------------------------------------------------------
// Bilinear gather + blend for one point at one level (fp16 SMEM table,
// fp32 arithmetic).
// ---------------------------------------------------------------------------
__device__ __forceinline__ float4 encode_one(const H4* __restrict__ s_tab,
                                             float xc, float yc, float scale) {
    // Match numpy's mul-then-add rounding (no FMA contraction).
    float px = __fadd_rn(__fmul_rn(xc, scale), 0.5f);
    float py = __fadd_rn(__fmul_rn(yc, scale), 0.5f);
    float fx = floorf(px);
    float fy = floorf(py);
    float wx = px - fx;
    float wy = py - fy;

    unsigned ix = (unsigned)(int)fx;
    unsigned iy = (unsigned)(int)fy;

    unsigned hy0 = iy * PRIME_Y;
    unsigned hy1 = hy0 + PRIME_Y;     // (iy+1)*PRIME_Y mod 2^32

    unsigned h00 = (ix        ^ hy0) & HASH_MASK;
    unsigned h10 = ((ix + 1u) ^ hy0) & HASH_MASK;
    unsigned h01 = (ix        ^ hy1) & HASH_MASK;
    unsigned h11 = ((ix + 1u) ^ hy1) & HASH_MASK;

    H4 q00 = s_tab[h00];
    H4 q10 = s_tab[h10];
    H4 q01 = s_tab[h01];
    H4 q11 = s_tab[h11];

    float2 f00l = __half22float2(q00.lo), f00h = __half22float2(q00.hi);
    float2 f10l = __half22float2(q10.lo), f10h = __half22float2(q10.hi);
    float2 f01l = __half22float2(q01.lo), f01h = __half22float2(q01.hi);
    float2 f11l = __half22float2(q11.lo), f11h = __half22float2(q11.hi);

    float ax = fmaf(wx, f10l.x - f00l.x, f00l.x);
    float ay = fmaf(wx, f10l.y - f00l.y, f00l.y);
    float az = fmaf(wx, f10h.x - f00h.x, f00h.x);
    float aw = fmaf(wx, f10h.y - f00h.y, f00h.y);
    float bx = fmaf(wx, f11l.x - f01l.x, f01l.x);
    float by = fmaf(wx, f11l.y - f01l.y, f01l.y);
    float bz = fmaf(wx, f11h.x - f01h.x, f01h.x);
    float bw = fmaf(wx, f11h.y - f01h.y, f01h.y);

    float4 r;
    r.x = fmaf(wy, bx - ax, ax);
    r.y = fmaf(wy, by - ay, ay);
    r.z = fmaf(wy, bz - az, az);
    r.w = fmaf(wy, bw - aw, aw);
    return r;
}

__device__ __forceinline__ uint32_t smem_u32(const void* p) {
    return (uint32_t)__cvta_generic_to_shared(p);
}

// ---------------------------------------------------------------------------
// Kernel 2 (level-pair TMA store path).
// smem: [0,128KB) fp16 table (2 levels), then 3 x 32KB staging. 224 KB.
// ---------------------------------------------------------------------------
__global__ void __launch_bounds__(THREADS, 1)
hash_encode_pair_kernel(const float2* __restrict__ x,
                        float4* __restrict__ out,     // tail fallback only
                        int N,
                        const __grid_constant__ CUtensorMap tmap)
{
    extern __shared__ char smem_raw[];
    H4*     s_tab = (H4*)smem_raw;                               // 2*8192
    float4* s_buf = (float4*)(smem_raw + 2 * HASHMAP_SIZE * 8);  // NBUF*TILE*2

    const int pair = blockIdx.y;        // levels 2*pair, 2*pair+1
    const int tid  = threadIdx.x;

    // Stage BOTH levels' blended fp16 tables into SMEM (coalesced 8B).
    const H4* lt = g_btable_h + (2 * pair) * HASHMAP_SIZE;
    #pragma unroll
    for (int i = tid; i < 2 * HASHMAP_SIZE; i += THREADS)
        s_tab[i] = lt[i];
    __syncthreads();

    // Per-level scales, matching numpy float64 exp2 path then fp32 cast.
    const float scale0 =
        (float)(exp2((double)(2 * pair)     * (6.0 / 7.0)) * 512.0 - 1.0);
    const float scale1 =
        (float)(exp2((double)(2 * pair + 1) * (6.0 / 7.0)) * 512.0 - 1.0);

    const int n_tiles = (N + TILE - 1) / TILE;
    const int stride  = gridDim.x;

    // Software pipeline: preload tile t0's coordinate (1 point per thread).
    int t = blockIdx.x;
    float2 c;
    if (t < n_tiles) {
        const int base = t * TILE;
        if (base + tid < N) c = __ldg(&x[base + tid]);
    }

    int it = 0;
    for (; t < n_tiles; t += stride, ++it) {
        const int base = t * TILE;
        const int rows = min(TILE, N - base);

        // Prefetch next tile's x -- latency hides under this tile's compute.
        const int tn = t + stride;
        float2 cn;
        if (tn < n_tiles) {
            const int nb = tn * TILE;
            if (nb + tid < N) cn = __ldg(&x[nb + tid]);
        }

        // Buffer reuse guard: buf(it) was handed to TMA at it-NBUF;
        // allow at most NBUF-1 = 2 pending store groups.
        if (tid == 0)
            asm volatile("cp.async.bulk.wait_group 2;" ::: "memory");
        __syncthreads();

        float4* buf = s_buf + (it % NBUF) * (TILE * 2);
        const int full = rows & ~(BOX_ROWS - 1);   // rows covered by TMA boxes

        if (tid < rows) {
            float4 r0 = encode_one(s_tab,                c.x, c.y, scale0);
            float4 r1 = encode_one(s_tab + HASHMAP_SIZE, c.x, c.y, scale1);
            if (tid < full) {
                buf[tid * 2]     = r0;   // 32B contiguous per point
                buf[tid * 2 + 1] = r1;
            } else {
                size_t o = (size_t)(base + tid) * N_LEVELS + 2 * pair;
                out[o]     = r0;
                out[o + 1] = r1;
            }
        }

        // Order generic-proxy STS before async-proxy TMA reads.
        asm volatile("fence.proxy.async;" ::: "memory");
        __syncthreads();

        if (tid == 0) {
            const int nb = full / BOX_ROWS;
            const uint32_t sa = smem_u32(buf);
            for (int j = 0; j < nb; ++j) {
                asm volatile(
                    "cp.async.bulk.tensor.3d.global.shared::cta.tile.bulk_group"
                    " [%0, {%1, %2, %3}], [%4];"
                    :: "l"(&tmap), "r"(0), "r"(pair), "r"(base + j * BOX_ROWS),
                       "r"(sa + (uint32_t)j * BOX_ROWS * 32u)
                    : "memory");
            }
            asm volatile("cp.async.bulk.commit_group;" ::: "memory");
        }

        c = cn;
    }

    // Drain all pending TMA stores before exit.
    if (tid == 0)
        asm volatile("cp.async.bulk.wait_group 0;" ::: "memory");
    __syncthreads();
}

// ---------------------------------------------------------------------------
// Kernel 2 (legacy STG fallback) -- used only if tensormap creation fails.
// ---------------------------------------------------------------------------
__global__ void __launch_bounds__(1024, 1)
hash_encode_kernel(const float4* __restrict__ x2, float4* __restrict__ out, int P)
{
    extern __shared__ char smem_raw[];
    H4* s_tab = (H4*)smem_raw;
    const int level = blockIdx.y;
    const H4* lt = g_btable_h + level * HASHMAP_SIZE;
    #pragma unroll
    for (int i = threadIdx.x; i < HASHMAP_SIZE; i += 1024)
        s_tab[i] = lt[i];
    __syncthreads();

    const float scale = (float)(exp2((double)level * (6.0 / 7.0)) * 512.0 - 1.0);
    const int chunk = (P + gridDim.x - 1) / gridDim.x;
    const int m0 = blockIdx.x * chunk;
    const int m1 = min(m0 + chunk, P);

    for (int m = m0 + threadIdx.x; m < m1; m += 1024) {
        float4 p = __ldg(&x2[m]);
        float4 r0 = encode_one(s_tab, p.x, p.y, scale);
        float4 r1 = encode_one(s_tab, p.z, p.w, scale);
        size_t n = (size_t)m * 2;
        out[n * N_LEVELS + level]       = r0;
        out[(n + 1) * N_LEVELS + level] = r1;
    }
}

// ---------------------------------------------------------------------------
// Host: tensormap encode via driver entry point (cudart-only lookup).
// ---------------------------------------------------------------------------
typedef CUresult (*EncodeTiledFn)(
    CUtensorMap*, CUtensorMapDataType, cuuint32_t, void*,
    const cuuint64_t*, const cuuint64_t*, const cuuint32_t*, const cuuint32_t*,
    CUtensorMapInterleave, CUtensorMapSwizzle, CUtensorMapL2promotion,
    CUtensorMapFloatOOBfill);

static EncodeTiledFn get_encode_fn() {
    void* p = nullptr;
#if CUDART_VERSION >= 12000
    cudaDriverEntryPointQueryResult qr;
    if (cudaGetDriverEntryPoint("cuTensorMapEncodeTiled", &p,
                                cudaEnableDefault, &qr) != cudaSuccess)
        return nullptr;
#else
    if (cudaGetDriverEntryPoint("cuTensorMapEncodeTiled", &p,
                                cudaEnableDefault) != cudaSuccess)
        return nullptr;
#endif
    return (EncodeTiledFn)p;
}

extern "C" void kernel_launch(void* const* d_in, const int* in_sizes, int n_in,
                              void* d_out, int out_size) {
    const float* x_ptr = nullptr;
    const float* t_ptr = nullptr;
    const float* table_ptr = nullptr;
    int N = 0;

    const int TABLE_ELEMS = TIME_RES * N_LEVELS * HASHMAP_SIZE * 4;  // 6,553,600

    for (int i = 0; i < n_in; i++) {
        int s = in_sizes[i];
        if (s == 1)                    t_ptr = (const float*)d_in[i];
        else if (s == TABLE_ELEMS)     table_ptr = (const float*)d_in[i];
        else { x_ptr = (const float*)d_in[i]; N = s / 2; }
    }

    // K1: temporal blend -> g_btable_h (fp16).
    blend_table_kernel<<<(N_LEVELS * HASHMAP_SIZE) / 256, 256>>>(table_ptr, t_ptr);

    // TMA path: out viewed as (8 floats, 4 level-pairs, N points).
    // Rows are now 32B (level pair per point) -> half the TMA row count.
    bool tma_ok = false;
    CUtensorMap tmap;
    EncodeTiledFn enc = get_encode_fn();
    if (enc) {
        cuuint64_t dims[3]    = {8, N_LEVELS / 2, (cuuint64_t)N};
        cuuint64_t strides[2] = {32, 128};               // bytes, dims 1..2
        cuuint32_t box[3]     = {8, 1, BOX_ROWS};
        cuuint32_t estr[3]    = {1, 1, 1};
        CUresult r = enc(&tmap, CU_TENSOR_MAP_DATA_TYPE_FLOAT32, 3, d_out,
                         dims, strides, box, estr,
                         CU_TENSOR_MAP_INTERLEAVE_NONE,
                         CU_TENSOR_MAP_SWIZZLE_NONE,
                         CU_TENSOR_MAP_L2_PROMOTION_L2_128B,
                         CU_TENSOR_MAP_FLOAT_OOB_FILL_NONE);
        tma_ok = (r == CUDA_SUCCESS);
    }

    if (tma_ok) {
        // 128 KB table (2 levels) + 3 x 32 KB staging = 224 KB -> 1 CTA/SM.
        const int SMEM = 2 * HASHMAP_SIZE * 8
                       + NBUF * TILE * 2 * (int)sizeof(float4);
        cudaFuncSetAttribute(hash_encode_pair_kernel,
                             cudaFuncAttributeMaxDynamicSharedMemorySize, SMEM);
        dim3 grid(37, N_LEVELS / 2);   // 148 CTAs = one wave
        hash_encode_pair_kernel<<<grid, THREADS, SMEM>>>(
            (const float2*)x_ptr, (float4*)d_out, N, tmap);
    } else {
        const int SMEM = HASHMAP_SIZE * 8;               // 64 KB
        cudaFuncSetAttribute(hash_encode_kernel,
                             cudaFuncAttributeMaxDynamicSharedMemorySize, SMEM);
        int P = N / 2;
        dim3 grid(18, N_LEVELS);
        hash_encode_kernel<<<grid, 1024, SMEM>>>(
            (const float4*)x_ptr, (float4*)d_out, P);
    }
}

// round 15
// speedup vs baseline: 1.6729x; 1.0065x over previous
#include <cuda_runtime.h>
#include <cuda.h>
#include <cuda_fp16.h>
#include <math.h>

// ---------------------------------------------------------------------------
// HashGridT: Instant-NGP 2D multires hash encoding + temporal interpolation
//
//   K1: blend the two time slices into one device-global fp16 table (512 KB).
//   K2 (R14): level-pair CTA (R13 win: 32B TMA rows, 8M rows) restructured
//       into TWO INDEPENDENT 512-THREAD PIPELINES per CTA with named
//       barriers. R13 ncu: issue 38.9%, L1 55% -> residual cost was CTA-wide
//       coupling (2x1024-thread barriers x 53 iters + 32-warp straggler +
//       tid0 serial TMA issue). Halves run disjoint half-tile streams with
//       private triple-buffered staging + private bulk-group counters; when
//       one half stalls at its barrier, the other's warps issue.
//       smem: 128KB table + 2 halves x 3 x 16KB staging = 224 KB, 1 CTA/SM,
//       grid (37 x 4 pairs) = 148 CTAs = one wave.
// ---------------------------------------------------------------------------

#define N_LEVELS     8
#define HASHMAP_SIZE 8192
#define HASH_MASK    8191u
#define PRIME_Y      2654435761u
#define TIME_RES     25
#define THREADS      1024
#define HALF         512             // threads per pipeline
#define HTILE        512             // points per half-tile (1 per thread)
#define NBUF         3               // staging buffers per half (wait_group 2)
#define BOX_ROWS     256             // TMA box: (8 floats, 1 pair, 256 points)

struct __align__(8) H4 { __half2 lo, hi; };

// Blended fp16 table: [level][hash] 4 feats. 512 KB static device global.
__device__ H4 g_btable_h[N_LEVELS * HASHMAP_SIZE];

// ---------------------------------------------------------------------------
// Kernel 1: temporal blend of the hash table (fp32 math, one fp16 round).
// ---------------------------------------------------------------------------
__global__ void blend_table_kernel(const float* __restrict__ table,
                                   const float* __restrict__ t_ptr) {
    int i = blockIdx.x * blockDim.x + threadIdx.x;  // 0 .. 65535

    float t   = *t_ptr;
    float idx = t * (float)(TIME_RES - 1);
    float fi1 = floorf(idx);
    float fi2 = ceilf(idx);
    int i1 = min(max((int)fi1, 0), TIME_RES - 1);
    int i2 = min(max((int)fi2, 0), TIME_RES - 1);
    float w2 = idx - fi1;
    float w1 = 1.0f - w2;

    const float4* tab = (const float4*)table;
    float4 a = tab[(size_t)i1 * (N_LEVELS * HASHMAP_SIZE) + i];
    float4 b = tab[(size_t)i2 * (N_LEVELS * HASHMAP_SIZE) + i];

    H4 h;
    h.lo = __floats2half2_rn(w1 * a.x + w2 * b.x, w1 * a.y + w2 * b.y);
    h.hi = __floats2half2_rn(w1 * a.z + w2 * b.z, w1 * a.w + w2 * b.w);
    g_btable_h[i] = h;
}

// ---------------------------------------------------------------------------
// Bilinear gather + blend for one point at one level (fp16 SMEM table,
// fp32 arithmetic).
// ---------------------------------------------------------------------------
__device__ __forceinline__ float4 encode_one(const H4* __restrict__ s_tab,
                                             float xc, float yc, float scale) {
    // Match numpy's mul-then-add rounding (no FMA contraction).
    float px = __fadd_rn(__fmul_rn(xc, scale), 0.5f);
    float py = __fadd_rn(__fmul_rn(yc, scale), 0.5f);
    float fx = floorf(px);
    float fy = floorf(py);
    float wx = px - fx;
    float wy = py - fy;

    unsigned ix = (unsigned)(int)fx;
    unsigned iy = (unsigned)(int)fy;

    unsigned hy0 = iy * PRIME_Y;
    unsigned hy1 = hy0 + PRIME_Y;     // (iy+1)*PRIME_Y mod 2^32

    unsigned h00 = (ix        ^ hy0) & HASH_MASK;
    unsigned h10 = ((ix + 1u) ^ hy0) & HASH_MASK;
    unsigned h01 = (ix        ^ hy1) & HASH_MASK;
    unsigned h11 = ((ix + 1u) ^ hy1) & HASH_MASK;

    H4 q00 = s_tab[h00];
    H4 q10 = s_tab[h10];
    H4 q01 = s_tab[h01];
    H4 q11 = s_tab[h11];

    float2 f00l = __half22float2(q00.lo), f00h = __half22float2(q00.hi);
    float2 f10l = __half22float2(q10.lo), f10h = __half22float2(q10.hi);
    float2 f01l = __half22float2(q01.lo), f01h = __half22float2(q01.hi);
    float2 f11l = __half22float2(q11.lo), f11h = __half22float2(q11.hi);

    float ax = fmaf(wx, f10l.x - f00l.x, f00l.x);
    float ay = fmaf(wx, f10l.y - f00l.y, f00l.y);
    float az = fmaf(wx, f10h.x - f00h.x, f00h.x);
    float aw = fmaf(wx, f10h.y - f00h.y, f00h.y);
    float bx = fmaf(wx, f11l.x - f01l.x, f01l.x);
    float by = fmaf(wx, f11l.y - f01l.y, f01l.y);
    float bz = fmaf(wx, f11h.x - f01h.x, f01h.x);
    float bw = fmaf(wx, f11h.y - f01h.y, f01h.y);

    float4 r;
    r.x = fmaf(wy, bx - ax, ax);
    r.y = fmaf(wy, by - ay, ay);
    r.z = fmaf(wy, bz - az, az);
    r.w = fmaf(wy, bw - aw, aw);
    return r;
}

__device__ __forceinline__ uint32_t smem_u32(const void* p) {
    return (uint32_t)__cvta_generic_to_shared(p);
}

#define BAR_SYNC(id) \
    asm volatile("bar.sync %0, %1;" :: "r"(id), "n"(HALF) : "memory")

// ---------------------------------------------------------------------------
// Kernel 2: level-pair encode, two independent 512-thread pipelines.
// smem: [0,128KB) fp16 tables (2 levels), then 2 x (3 x 16KB) staging.
// ---------------------------------------------------------------------------
__global__ void __launch_bounds__(THREADS, 1)
hash_encode_pair_kernel(const float2* __restrict__ x,
                        float4* __restrict__ out,     // tail fallback only
                        int N,
                        const __grid_constant__ CUtensorMap tmap)
{
    extern __shared__ char smem_raw[];
    H4*     s_tab = (H4*)smem_raw;                               // 2*8192
    float4* s_buf = (float4*)(smem_raw + 2 * HASHMAP_SIZE * 8);

    const int pair = blockIdx.y;        // levels 2*pair, 2*pair+1
    const int tid  = threadIdx.x;
    const int h    = tid >> 9;          // pipeline half: 0 or 1
    const int ltid = tid & (HALF - 1);
    const int bar  = 1 + h;             // named barrier id for this half

    // Stage BOTH levels' blended fp16 tables into SMEM (coalesced 8B).
    const H4* lt = g_btable_h + (2 * pair) * HASHMAP_SIZE;
    #pragma unroll
    for (int i = tid; i < 2 * HASHMAP_SIZE; i += THREADS)
        s_tab[i] = lt[i];
    __syncthreads();   // the ONLY CTA-wide barrier

    // Per-level scales, matching numpy float64 exp2 path then fp32 cast.
    const float scale0 =
        (float)(exp2((double)(2 * pair)     * (6.0 / 7.0)) * 512.0 - 1.0);
    const float scale1 =
        (float)(exp2((double)(2 * pair + 1) * (6.0 / 7.0)) * 512.0 - 1.0);

    // This half's private staging: NBUF buffers of HTILE rows x 32B.
    float4* hbuf = s_buf + h * (NBUF * HTILE * 2);

    const int n_tiles = (N + 2 * HTILE - 1) / (2 * HTILE);  // 1024-pt tiles
    const int stride  = gridDim.x;

    // Software pipeline: preload first half-tile's coordinate.
    int t = blockIdx.x;
    float2 c;
    if (t < n_tiles) {
        const int base = t * (2 * HTILE) + h * HTILE;
        if (base + ltid < N) c = __ldg(&x[base + ltid]);
    }

    int it = 0;
    for (; t < n_tiles; t += stride, ++it) {
        const int base = t * (2 * HTILE) + h * HTILE;
        const int rows = max(0, min(HTILE, N - base));
        const int full = rows & ~(BOX_ROWS - 1);

        // Prefetch next half-tile's x -- hides under this tile's compute.
        const int tn = t + stride;
        float2 cn;
        if (tn < n_tiles) {
            const int nb = tn * (2 * HTILE) + h * HTILE;
            if (nb + ltid < N) cn = __ldg(&x[nb + ltid]);
        }

        // Reuse guard: buffer (it % NBUF) was handed to TMA at it-NBUF;
        // allow at most NBUF-1 pending groups. Per-half leader only.
        if (ltid == 0)
            asm volatile("cp.async.bulk.wait_group 2;" ::: "memory");
        BAR_SYNC(bar);

        float4* buf = hbuf + (it % NBUF) * (HTILE * 2);

        if (ltid < rows) {
            float4 r0 = encode_one(s_tab,                c.x, c.y, scale0);
            float4 r1 = encode_one(s_tab + HASHMAP_SIZE, c.x, c.y, scale1);
            if (ltid < full) {
                buf[ltid * 2]     = r0;   // 32B contiguous per point
                buf[ltid * 2 + 1] = r1;
            } else {
                size_t o = (size_t)(base + ltid) * N_LEVELS + 2 * pair;
                out[o]     = r0;
                out[o + 1] = r1;
            }
        }

        // Order generic-proxy STS before async-proxy TMA reads.
        asm volatile("fence.proxy.async;" ::: "memory");
        BAR_SYNC(bar);

        if (ltid == 0) {
            const int nb = full / BOX_ROWS;
            const uint32_t sa = smem_u32(buf);
            for (int j = 0; j < nb; ++j) {
                asm volatile(
                    "cp.async.bulk.tensor.3d.global.shared::cta.tile.bulk_group"
                    " [%0, {%1, %2, %3}], [%4];"
                    :: "l"(&tmap), "r"(0), "r"(pair), "r"(base + j * BOX_ROWS),
                       "r"(sa + (uint32_t)j * BOX_ROWS * 32u)
                    : "memory");
            }
            asm volatile("cp.async.bulk.commit_group;" ::: "memory");
        }

        c = cn;
    }

    // Drain this half's pending TMA stores before exit.
    if (ltid == 0)
        asm volatile("cp.async.bulk.wait_group 0;" ::: "memory");
    BAR_SYNC(bar);
}

// ---------------------------------------------------------------------------
// Kernel 2 (legacy STG fallback) -- used only if tensormap creation fails.
// ---------------------------------------------------------------------------
__global__ void __launch_bounds__(1024, 1)
hash_encode_kernel(const float4* __restrict__ x2, float4* __restrict__ out, int P)
{
    extern __shared__ char smem_raw[];
    H4* s_tab = (H4*)smem_raw;
    const int level = blockIdx.y;
    const H4* lt = g_btable_h + level * HASHMAP_SIZE;
    #pragma unroll
    for (int i = threadIdx.x; i < HASHMAP_SIZE; i += 1024)
        s_tab[i] = lt[i];
    __syncthreads();

    const float scale = (float)(exp2((double)level * (6.0 / 7.0)) * 512.0 - 1.0);
    const int chunk = (P + gridDim.x - 1) / gridDim.x;
    const int m0 = blockIdx.x * chunk;
    const int m1 = min(m0 + chunk, P);

    for (int m = m0 + threadIdx.x; m < m1; m += 1024) {
        float4 p = __ldg(&x2[m]);
        float4 r0 = encode_one(s_tab, p.x, p.y, scale);
        float4 r1 = encode_one(s_tab, p.z, p.w, scale);
        size_t n = (size_t)m * 2;
        out[n * N_LEVELS + level]       = r0;
        out[(n + 1) * N_LEVELS + level] = r1;
    }
}

// ---------------------------------------------------------------------------
// Host: tensormap encode via driver entry point (cudart-only lookup).
// ---------------------------------------------------------------------------
typedef CUresult (*EncodeTiledFn)(
    CUtensorMap*, CUtensorMapDataType, cuuint32_t, void*,
    const cuuint64_t*, const cuuint64_t*, const cuuint32_t*, const cuuint32_t*,
    CUtensorMapInterleave, CUtensorMapSwizzle, CUtensorMapL2promotion,
    CUtensorMapFloatOOBfill);

static EncodeTiledFn get_encode_fn() {
    void* p = nullptr;
#if CUDART_VERSION >= 12000
    cudaDriverEntryPointQueryResult qr;
    if (cudaGetDriverEntryPoint("cuTensorMapEncodeTiled", &p,
                                cudaEnableDefault, &qr) != cudaSuccess)
        return nullptr;
#else
    if (cudaGetDriverEntryPoint("cuTensorMapEncodeTiled", &p,
                                cudaEnableDefault) != cudaSuccess)
        return nullptr;
#endif
    return (EncodeTiledFn)p;
}

extern "C" void kernel_launch(void* const* d_in, const int* in_sizes, int n_in,
                              void* d_out, int out_size) {
    const float* x_ptr = nullptr;
    const float* t_ptr = nullptr;
    const float* table_ptr = nullptr;
    int N = 0;

    const int TABLE_ELEMS = TIME_RES * N_LEVELS * HASHMAP_SIZE * 4;  // 6,553,600

    for (int i = 0; i < n_in; i++) {
        int s = in_sizes[i];
        if (s == 1)                    t_ptr = (const float*)d_in[i];
        else if (s == TABLE_ELEMS)     table_ptr = (const float*)d_in[i];
        else { x_ptr = (const float*)d_in[i]; N = s / 2; }
    }

    // K1: temporal blend -> g_btable_h (fp16).
    blend_table_kernel<<<(N_LEVELS * HASHMAP_SIZE) / 256, 256>>>(table_ptr, t_ptr);

    // TMA path: out viewed as (8 floats, 4 level-pairs, N points); 32B rows.
    bool tma_ok = false;
    CUtensorMap tmap;
    EncodeTiledFn enc = get_encode_fn();
    if (enc) {
        cuuint64_t dims[3]    = {8, N_LEVELS / 2, (cuuint64_t)N};
        cuuint64_t strides[2] = {32, 128};               // bytes, dims 1..2
        cuuint32_t box[3]     = {8, 1, BOX_ROWS};
        cuuint32_t estr[3]    = {1, 1, 1};
        CUresult r = enc(&tmap, CU_TENSOR_MAP_DATA_TYPE_FLOAT32, 3, d_out,
                         dims, strides, box, estr,
                         CU_TENSOR_MAP_INTERLEAVE_NONE,
                         CU_TENSOR_MAP_SWIZZLE_NONE,
                         CU_TENSOR_MAP_L2_PROMOTION_L2_128B,
                         CU_TENSOR_MAP_FLOAT_OOB_FILL_NONE);
        tma_ok = (r == CUDA_SUCCESS);
    }

    if (tma_ok) {
        // 128 KB table + 2 halves x 3 x 16 KB staging = 224 KB -> 1 CTA/SM.
        const int SMEM = 2 * HASHMAP_SIZE * 8
                       + 2 * NBUF * HTILE * 2 * (int)sizeof(float4);
        cudaFuncSetAttribute(hash_encode_pair_kernel,
                             cudaFuncAttributeMaxDynamicSharedMemorySize, SMEM);
        dim3 grid(37, N_LEVELS / 2);   // 148 CTAs = one wave
        hash_encode_pair_kernel<<<grid, THREADS, SMEM>>>(
            (const float2*)x_ptr, (float4*)d_out, N, tmap);
    } else {
        const int SMEM = HASHMAP_SIZE * 8;               // 64 KB
        cudaFuncSetAttribute(hash_encode_kernel,
                             cudaFuncAttributeMaxDynamicSharedMemorySize, SMEM);
        int P = N / 2;
        dim3 grid(18, N_LEVELS);
        hash_encode_kernel<<<grid, 1024, SMEM>>>(
            (const float4*)x_ptr, (float4*)d_out, P);
    }
}